// round 13
// baseline (speedup 1.0000x reference)
#include <cuda_runtime.h>
#include <cuda_fp16.h>
#include <math.h>
#include <stdint.h>

#define N_ATOM 512
#define D_MODEL 512
#define N_HEAD 16
#define K_GAUSS 128
#define N_LAYER 4
#define NP1 513
#define NPAD 528
#define HD (N_HEAD * D_MODEL)
#define NCELL (N_ATOM * N_ATOM)

__device__ float g_S[N_ATOM * K_GAUSS];
__device__ float g_bias[(size_t)N_HEAD * NCELL];
__device__ int   g_et[NCELL];
__device__ int   g_deg[N_ATOM];
__device__ float g_x[NP1 * D_MODEL];
__device__ float g_q[(size_t)NP1 * HD];
__device__ float g_k[(size_t)NP1 * HD];
__device__ float g_v[(size_t)NPAD * HD];   // rows 513..527 stay zero
__device__ float g_o[(size_t)NP1 * HD];
__device__ float g_attn[(size_t)N_HEAD * NP1 * NPAD];
__device__ float g_z[NP1 * D_MODEL];
__device__ float g_h1[NP1 * D_MODEL];

__global__ void zero_int_kernel(int* p, int n) {
    int i = blockIdx.x * blockDim.x + threadIdx.x;
    if (i < n) p[i] = 0;
}
__global__ void zero_float_kernel(float* p, int n) {
    int i = blockIdx.x * blockDim.x + threadIdx.x;
    if (i < n) p[i] = 0.f;
}

__global__ void scatter_kernel(const int* __restrict__ edge_index,
                               const int* __restrict__ types, int E_) {
    if (blockIdx.x == 0 && threadIdx.x == 0) {
        for (int e = 0; e < E_; e++)
            g_et[edge_index[e] * N_ATOM + edge_index[E_ + e]] = types[e];
        for (int e = 0; e < E_; e++)
            g_et[edge_index[E_ + e] * N_ATOM + edge_index[e]] = types[e];
    }
}

__global__ void degree_kernel() {
    int i = blockIdx.x;
    int c = 0;
    for (int j = threadIdx.x; j < N_ATOM; j += 256)
        c += (g_et[i * N_ATOM + j] != 0);
    __shared__ int sh[256];
    sh[threadIdx.x] = c;
    __syncthreads();
    for (int s = 128; s > 0; s >>= 1) {
        if (threadIdx.x < s) sh[threadIdx.x] += sh[threadIdx.x + s];
        __syncthreads();
    }
    if (threadIdx.x == 0) g_deg[i] = sh[0];
}

#define MMAF16(d, a, b) asm volatile( \
    "mma.sync.aligned.m16n8k16.row.col.f32.f16.f16.f32 " \
    "{%0,%1,%2,%3},{%4,%5,%6,%7},{%8,%9},{%0,%1,%2,%3};\n" \
    : "+f"(d[0]), "+f"(d[1]), "+f"(d[2]), "+f"(d[3]) \
    : "r"(a[0]), "r"(a[1]), "r"(a[2]), "r"(a[3]), "r"(b[0]), "r"(b[1]))

#define LDSM_X4(r0, r1, r2, r3, addr) asm volatile( \
    "ldmatrix.sync.aligned.m8n8.x4.shared.b16 {%0,%1,%2,%3}, [%4];\n" \
    : "=r"(r0), "=r"(r1), "=r"(r2), "=r"(r3) : "r"(addr))

__device__ __forceinline__ uint32_t s2u(const void* p) {
    return (uint32_t)__cvta_generic_to_shared(p);
}

__device__ __forceinline__ void cvt_split2(__half* hi, __half* lo, float x0, float x1) {
    __half h0 = __float2half_rn(x0);
    __half h1 = __float2half_rn(x1);
    *(__half2*)hi = __halves2half2(h0, h1);
    *(__half2*)lo = __halves2half2(__float2half_rn(x0 - __half2float(h0)),
                                   __float2half_rn(x1 - __half2float(h1)));
}

// ---- fused preprocessing: psi on-the-fly -> MMA(pW1) -> gelu -> @pW2 + spd + edge
#define FUSED_SMEM 88576

__global__ __launch_bounds__(256) void fused_bias_kernel(
    const float* __restrict__ pos,
    const float* __restrict__ gamma_tab, const float* __restrict__ beta_tab,
    const float* __restrict__ means, const float* __restrict__ stds,
    const float* __restrict__ pW1, const float* __restrict__ pW2,
    const int* __restrict__ spatial_pos, const int* __restrict__ edge_input,
    const float* __restrict__ spd_tab, const float* __restrict__ edge_tab,
    const float* __restrict__ edge_dis)
{
    extern __shared__ char dyn[];
    float* means_s = (float*)dyn;
    float* isd_s   = means_s + 128;
    float* normc_s = isd_s + 128;
    float* xg_s    = normc_s + 128;
    float* S_s     = xg_s + 128;
    float* etab_s  = S_s + 128;
    float* pw2_s   = etab_s + 512;
    float* ew_s    = pw2_s + 2048;
    char*  scratch = (char*)(ew_s + 2048);
    __half* stA_hi = (__half*)scratch;
    __half* stA_lo = stA_hi + 6144;
    __half* stB_hi = stA_lo + 6144;
    __half* stB_lo = stB_hi + 6144;
    float*  Tsm    = (float*)scratch;

    int tid = threadIdx.x;
    long cell0 = (long)blockIdx.x * 128;
    int i_row = (int)(cell0 >> 9);

    if (tid < 128) {
        float sd = fabsf(stds[tid]) + 0.01f;
        means_s[tid] = means[tid];
        isd_s[tid] = 1.f / sd;
        normc_s[tid] = 0.3989422804014327f / sd;
        S_s[tid] = 0.f;
        int j = (int)(cell0 & 511) + tid;
        float dx = pos[i_row * 3 + 0] - pos[j * 3 + 0];
        float dy = pos[i_row * 3 + 1] - pos[j * 3 + 1];
        float dz = pos[i_row * 3 + 2] - pos[j * 3 + 2];
        float dist = sqrtf(dx * dx + dy * dy + dz * dz + 1e-12f);
        int t = g_et[cell0 + tid];
        xg_s[tid] = gamma_tab[t] * dist + beta_tab[t];
    }
    for (int i2 = tid; i2 < 512; i2 += 256) etab_s[i2] = edge_tab[i2];
    for (int i2 = tid; i2 < 2048; i2 += 256) pw2_s[i2] = pW2[i2];
    for (int i2 = tid; i2 < 2048; i2 += 256) ew_s[i2] = edge_dis[i2];
    __syncthreads();

    int wid = tid >> 5, lane = tid & 31;
    int wm = wid >> 2, wn = wid & 3;
    int g = lane >> 2, tg = lane & 3;

    float acc[4][4][4];
    #pragma unroll
    for (int a = 0; a < 4; a++)
        #pragma unroll
        for (int b = 0; b < 4; b++)
            #pragma unroll
            for (int t = 0; t < 4; t++) acc[a][b][t] = 0.f;

    float4 ra[2], rb[2];

    auto computeA = [&](int c) {
        int k0 = c * 16;
        #pragma unroll
        for (int it = 0; it < 2; it++) {
            int idx = it * 256 + tid;
            int r = idx >> 2, c4 = idx & 3;
            float xgr = xg_s[r];
            float e[4];
            #pragma unroll
            for (int q = 0; q < 4; q++) {
                int kk = k0 + c4 * 4 + q;
                float u = (xgr - means_s[kk]) * isd_s[kk];
                e[q] = normc_s[kk] * expf(-0.5f * u * u);
            }
            ra[it] = make_float4(e[0], e[1], e[2], e[3]);
        }
        float p0 = ra[0].x + ra[1].x, p1 = ra[0].y + ra[1].y;
        float p2 = ra[0].z + ra[1].z, p3 = ra[0].w + ra[1].w;
        #pragma unroll
        for (int m = 4; m <= 16; m <<= 1) {
            p0 += __shfl_xor_sync(0xffffffffu, p0, m);
            p1 += __shfl_xor_sync(0xffffffffu, p1, m);
            p2 += __shfl_xor_sync(0xffffffffu, p2, m);
            p3 += __shfl_xor_sync(0xffffffffu, p3, m);
        }
        if (lane < 4) {
            atomicAdd(&S_s[k0 + lane * 4 + 0], p0);
            atomicAdd(&S_s[k0 + lane * 4 + 1], p1);
            atomicAdd(&S_s[k0 + lane * 4 + 2], p2);
            atomicAdd(&S_s[k0 + lane * 4 + 3], p3);
        }
    };
    auto loadB = [&](int c) {
        int k0 = c * 16;
        #pragma unroll
        for (int it = 0; it < 2; it++) {
            int idx = it * 256 + tid;
            int r = idx >> 2, c4 = idx & 3;
            rb[it] = *(const float4*)(pW1 + r * 128 + k0 + c4 * 4);
        }
    };
    auto storeAB = [&](int st) {
        #pragma unroll
        for (int it = 0; it < 2; it++) {
            int idx = it * 256 + tid;
            int r = idx >> 2, c4 = idx & 3;
            __half* pah = stA_hi + st * 3072 + r * 24 + c4 * 4;
            __half* pal = stA_lo + st * 3072 + r * 24 + c4 * 4;
            cvt_split2(pah, pal, ra[it].x, ra[it].y);
            cvt_split2(pah + 2, pal + 2, ra[it].z, ra[it].w);
            __half* pbh = stB_hi + st * 3072 + r * 24 + c4 * 4;
            __half* pbl = stB_lo + st * 3072 + r * 24 + c4 * 4;
            cvt_split2(pbh, pbl, rb[it].x, rb[it].y);
            cvt_split2(pbh + 2, pbl + 2, rb[it].z, rb[it].w);
        }
    };

    computeA(0); loadB(0); storeAB(0);
    for (int c = 0; c < 8; c++) {
        __syncthreads();
        int st = c & 1;
        if (c < 7) { computeA(c + 1); loadB(c + 1); }
        uint32_t ah[4][4], al[4][4], bh[4][2], bl[4][2];
        #pragma unroll
        for (int mt = 0; mt < 4; mt++) {
            int row = wm * 64 + mt * 16 + (lane & 15);
            int colb = (lane >> 4) << 3;
            uint32_t ad = s2u(stA_hi + st * 3072 + row * 24 + colb);
            LDSM_X4(ah[mt][0], ah[mt][1], ah[mt][2], ah[mt][3], ad);
            ad = s2u(stA_lo + st * 3072 + row * 24 + colb);
            LDSM_X4(al[mt][0], al[mt][1], al[mt][2], al[mt][3], ad);
        }
        #pragma unroll
        for (int np = 0; np < 2; np++) {
            int brow = wn * 32 + np * 16 + (lane & 7) + ((lane >> 4) << 3);
            int bcol = ((lane >> 3) & 1) * 8;
            uint32_t bd = s2u(stB_hi + st * 3072 + brow * 24 + bcol);
            LDSM_X4(bh[2 * np][0], bh[2 * np][1], bh[2 * np + 1][0], bh[2 * np + 1][1], bd);
            bd = s2u(stB_lo + st * 3072 + brow * 24 + bcol);
            LDSM_X4(bl[2 * np][0], bl[2 * np][1], bl[2 * np + 1][0], bl[2 * np + 1][1], bd);
        }
        #pragma unroll
        for (int mt = 0; mt < 4; mt++)
            #pragma unroll
            for (int nt = 0; nt < 4; nt++) {
                MMAF16(acc[mt][nt], ah[mt], bh[nt]);
                MMAF16(acc[mt][nt], ah[mt], bl[nt]);
                MMAF16(acc[mt][nt], al[mt], bh[nt]);
            }
        if (c < 7) storeAB((c + 1) & 1);
    }
    __syncthreads();

    #pragma unroll
    for (int mt = 0; mt < 4; mt++)
        #pragma unroll
        for (int nt = 0; nt < 4; nt++)
            #pragma unroll
            for (int t = 0; t < 4; t++) {
                int gm = wm * 64 + mt * 16 + g + ((t >= 2) ? 8 : 0);
                int gn = wn * 32 + nt * 8 + tg * 2 + (t & 1);
                float v = acc[mt][nt][t];
                Tsm[gm * 132 + gn] = 0.5f * v * (1.f + erff(v * 0.7071067811865476f));
            }
    __syncthreads();

    int h = tid >> 4;
    for (int it2 = 0; it2 < 8; it2++) {
        int cl = (tid & 15) + it2 * 16;
        long cellg = cell0 + cl;
        float a2 = 0.f;
        const float* trow = &Tsm[cl * 132];
        const float* prow = &pw2_s[h * 128];
        #pragma unroll 8
        for (int k2 = 0; k2 < 128; k2++) a2 += trow[k2] * prow[k2];
        int sp = spatial_pos[cellg];
        a2 += spd_tab[sp * 16 + h];
        float esum = 0.f;
        for (int m = 0; m < 8; m++) {
            int ei = edge_input[cellg * 8 + m];
            const float* ewm = &ew_s[m * 256];
            #pragma unroll
            for (int hh = 0; hh < 16; hh++)
                esum += etab_s[ei * 16 + hh] * ewm[hh * 16 + h];
        }
        float spf = (sp == 0) ? 1.f : (float)sp;
        g_bias[(size_t)h * NCELL + cellg] = a2 + esum / spf;
    }
    if (tid < 128) atomicAdd(&g_S[i_row * 128 + tid], S_s[tid]);
}

__global__ void xinit_kernel(const float* __restrict__ atoms_x,
                             const int* __restrict__ atoms,
                             const float* __restrict__ atom_tab,
                             const float* __restrict__ degree_tab,
                             const float* __restrict__ w3d,
                             const float* __restrict__ cls) {
    int i = blockIdx.x;
    __shared__ float Ssh[128];
    if (threadIdx.x < 128) Ssh[threadIdx.x] = g_S[i * K_GAUSS + threadIdx.x];
    __syncthreads();
    int a = atoms[i], dgi = g_deg[i];
    for (int d = threadIdx.x; d < D_MODEL; d += blockDim.x) {
        float acc = 0.f;
        const float* wrow = w3d + (size_t)d * K_GAUSS;
        #pragma unroll 8
        for (int k = 0; k < 128; k++) acc += Ssh[k] * wrow[k];
        g_x[(i + 1) * D_MODEL + d] = atoms_x[i * D_MODEL + d]
                                   + atom_tab[a * D_MODEL + d]
                                   + degree_tab[dgi * D_MODEL + d] + acc;
    }
    if (i == 0)
        for (int d = threadIdx.x; d < D_MODEL; d += blockDim.x)
            g_x[d] = cls[d];
}

// ---- fp16x3 GEMM, scalar smem fragment loads, double-buffered, 2 CTAs/SM ------
template <int BM, int BN, int EPI, int BLOAD, bool ATOMIC, bool VECA>
__global__ __launch_bounds__(256, 2) void mma_gemm(
    const float* __restrict__ Ag, const float* __restrict__ Bg,
    float* __restrict__ Cg, const float* __restrict__ biasg,
    int M, int N, int K, int lda, int ldb, int ldc,
    long strA, long strB, long strC, long strBias, float alpha) {

    constexpr int KC = 16;
    constexpr int KS = 24;
    constexpr int WM = BM / 2;
    constexpr int WN = BN / 4;
    constexpr int MT = WM / 16;
    constexpr int NT = WN / 8;
    constexpr int A4 = (BM * KC) / (4 * 256);
    constexpr int B4 = (BN * KC) / (4 * 256);
    constexpr int NB4 = BN / 4;

    __shared__ __align__(16) __half smA_hi[2][BM][KS];
    __shared__ __align__(16) __half smA_lo[2][BM][KS];
    __shared__ __align__(16) __half smB_hi[2][BN][KS];
    __shared__ __align__(16) __half smB_lo[2][BN][KS];

    int bz = blockIdx.z;
    const float* A = Ag + (long)bz * strA;
    const float* B = Bg + (long)bz * strB;
    float* C = Cg + (long)bz * strC;
    const float* bias = (EPI == 2) ? (biasg + (long)bz * strBias) : nullptr;

    int bm = blockIdx.y * BM;
    int bn = blockIdx.x * BN;
    int tid = threadIdx.x;
    int wid = tid >> 5, lane = tid & 31;
    int wm = wid >> 2, wn = wid & 3;
    int g = lane >> 2, tg = lane & 3;

    float acc[MT][NT][4];
    #pragma unroll
    for (int i = 0; i < MT; i++)
        #pragma unroll
        for (int j = 0; j < NT; j++)
            #pragma unroll
            for (int t = 0; t < 4; t++) acc[i][j][t] = 0.f;

    float4 ra[A4], rb[B4];
    int nc = (K + KC - 1) / KC;

    auto loadA = [&](int c) {
        int k0 = c * KC;
        #pragma unroll
        for (int it = 0; it < A4; it++) {
            int idx = it * 256 + tid;
            int r = idx >> 2, c4 = idx & 3;
            int gm = bm + r;
            if (VECA) {
                if (gm < M)
                    ra[it] = *(const float4*)(A + (long)gm * lda + k0 + c4 * 4);
                else
                    ra[it] = make_float4(0.f, 0.f, 0.f, 0.f);
            } else {
                float e[4];
                #pragma unroll
                for (int q2 = 0; q2 < 4; q2++) {
                    int gk = k0 + c4 * 4 + q2;
                    e[q2] = (gm < M && gk < K) ? A[(long)gm * lda + gk] : 0.f;
                }
                ra[it] = make_float4(e[0], e[1], e[2], e[3]);
            }
        }
    };
    auto loadB = [&](int c) {
        int k0 = c * KC;
        if (BLOAD == 0) {
            #pragma unroll
            for (int it = 0; it < B4; it++) {
                int idx = it * 256 + tid;
                int r = idx >> 2, c4 = idx & 3;
                int gn = bn + r;
                if (gn < N)
                    rb[it] = *(const float4*)(B + (long)gn * ldb + k0 + c4 * 4);
                else
                    rb[it] = make_float4(0.f, 0.f, 0.f, 0.f);
            }
        } else {
            #pragma unroll
            for (int it = 0; it < B4; it++) {
                int idx = it * 256 + tid;
                int kk = idx / NB4, n4 = idx % NB4;
                int gk = k0 + kk;
                if (gk < K)
                    rb[it] = *(const float4*)(B + (long)gk * ldb + bn + n4 * 4);
                else
                    rb[it] = make_float4(0.f, 0.f, 0.f, 0.f);
            }
        }
    };
    auto storeAB = [&](int st) {
        #pragma unroll
        for (int it = 0; it < A4; it++) {
            int idx = it * 256 + tid;
            int r = idx >> 2, c4 = idx & 3;
            cvt_split2(&smA_hi[st][r][c4 * 4], &smA_lo[st][r][c4 * 4], ra[it].x, ra[it].y);
            cvt_split2(&smA_hi[st][r][c4 * 4 + 2], &smA_lo[st][r][c4 * 4 + 2], ra[it].z, ra[it].w);
        }
        if (BLOAD == 0) {
            #pragma unroll
            for (int it = 0; it < B4; it++) {
                int idx = it * 256 + tid;
                int r = idx >> 2, c4 = idx & 3;
                cvt_split2(&smB_hi[st][r][c4 * 4], &smB_lo[st][r][c4 * 4], rb[it].x, rb[it].y);
                cvt_split2(&smB_hi[st][r][c4 * 4 + 2], &smB_lo[st][r][c4 * 4 + 2], rb[it].z, rb[it].w);
            }
        } else {
            #pragma unroll
            for (int it = 0; it < B4; it++) {
                int idx = it * 256 + tid;
                int kk = idx / NB4, n4 = idx % NB4;
                float e[4] = {rb[it].x, rb[it].y, rb[it].z, rb[it].w};
                #pragma unroll
                for (int q2 = 0; q2 < 4; q2++) {
                    __half hh = __float2half_rn(e[q2]);
                    smB_hi[st][n4 * 4 + q2][kk] = hh;
                    smB_lo[st][n4 * 4 + q2][kk] = __float2half_rn(e[q2] - __half2float(hh));
                }
            }
        }
    };

    loadA(0); loadB(0);
    storeAB(0);

    for (int c = 0; c < nc; c++) {
        __syncthreads();
        int st = c & 1;
        if (c + 1 < nc) { loadA(c + 1); loadB(c + 1); }

        uint32_t ah[MT][4], al[MT][4], bh[NT][2], bl[NT][2];
        int cc = tg * 2;
        #pragma unroll
        for (int mt = 0; mt < MT; mt++) {
            int row = wm * WM + mt * 16 + g;
            ah[mt][0] = *(const uint32_t*)&smA_hi[st][row][cc];
            ah[mt][1] = *(const uint32_t*)&smA_hi[st][row + 8][cc];
            ah[mt][2] = *(const uint32_t*)&smA_hi[st][row][cc + 8];
            ah[mt][3] = *(const uint32_t*)&smA_hi[st][row + 8][cc + 8];
            al[mt][0] = *(const uint32_t*)&smA_lo[st][row][cc];
            al[mt][1] = *(const uint32_t*)&smA_lo[st][row + 8][cc];
            al[mt][2] = *(const uint32_t*)&smA_lo[st][row][cc + 8];
            al[mt][3] = *(const uint32_t*)&smA_lo[st][row + 8][cc + 8];
        }
        #pragma unroll
        for (int nt = 0; nt < NT; nt++) {
            int col = wn * WN + nt * 8 + g;
            bh[nt][0] = *(const uint32_t*)&smB_hi[st][col][cc];
            bh[nt][1] = *(const uint32_t*)&smB_hi[st][col][cc + 8];
            bl[nt][0] = *(const uint32_t*)&smB_lo[st][col][cc];
            bl[nt][1] = *(const uint32_t*)&smB_lo[st][col][cc + 8];
        }
        #pragma unroll
        for (int mt = 0; mt < MT; mt++)
            #pragma unroll
            for (int nt = 0; nt < NT; nt++) {
                MMAF16(acc[mt][nt], ah[mt], bh[nt]);
                MMAF16(acc[mt][nt], ah[mt], bl[nt]);
                MMAF16(acc[mt][nt], al[mt], bh[nt]);
            }

        if (c + 1 < nc) storeAB((c + 1) & 1);
    }

    #pragma unroll
    for (int mt = 0; mt < MT; mt++) {
        #pragma unroll
        for (int nt = 0; nt < NT; nt++) {
            int r0 = bm + wm * WM + mt * 16 + g;
            int c0 = bn + wn * WN + nt * 8 + tg * 2;
            #pragma unroll
            for (int t = 0; t < 4; t++) {
                int gm = r0 + (t >= 2 ? 8 : 0);
                int gn = c0 + (t & 1);
                if (gm >= M || gn >= N) continue;
                float vv = acc[mt][nt][t] * alpha;
                if (EPI == 1) {
                    vv = 0.5f * vv * (1.f + erff(vv * 0.7071067811865476f));
                } else if (EPI == 2) {
                    if (gm >= 1 && gn >= 1)
                        vv += bias[(long)(gm - 1) * N_ATOM + (gn - 1)];
                }
                if (ATOMIC) atomicAdd(&C[(long)gm * ldc + gn], vv);
                else C[(long)gm * ldc + gn] = vv;
            }
        }
    }
}

__global__ void softmax_kernel() {
    long row = blockIdx.x;
    float* p = g_attn + row * NPAD;
    int tid = threadIdx.x;
    __shared__ float sh[256];
    float mx = -1e30f;
    for (int m = tid; m < NP1; m += 256) mx = fmaxf(mx, p[m]);
    sh[tid] = mx; __syncthreads();
    for (int s = 128; s > 0; s >>= 1) {
        if (tid < s) sh[tid] = fmaxf(sh[tid], sh[tid + s]);
        __syncthreads();
    }
    mx = sh[0]; __syncthreads();
    float sum = 0.f;
    for (int m = tid; m < NP1; m += 256) {
        float e = expf(p[m] - mx);
        p[m] = e;
        sum += e;
    }
    sh[tid] = sum; __syncthreads();
    for (int s = 128; s > 0; s >>= 1) {
        if (tid < s) sh[tid] += sh[tid + s];
        __syncthreads();
    }
    float inv = 1.f / sh[0];
    __syncthreads();
    for (int m = tid; m < NP1; m += 256) p[m] *= inv;
    if (tid < NPAD - NP1) p[NP1 + tid] = 0.f;
}

__global__ void add_ln_kernel(const float* __restrict__ xin, const float* __restrict__ z,
                              const float* __restrict__ s, const float* __restrict__ b,
                              float* __restrict__ xout) {
    int row = blockIdx.x, tid = threadIdx.x;
    float v0 = xin[row * D_MODEL + tid] + z[row * D_MODEL + tid];
    float v1 = xin[row * D_MODEL + tid + 256] + z[row * D_MODEL + tid + 256];
    __shared__ float sh[256];
    sh[tid] = v0 + v1; __syncthreads();
    for (int st = 128; st > 0; st >>= 1) {
        if (tid < st) sh[tid] += sh[tid + st];
        __syncthreads();
    }
    float mu = sh[0] * (1.f / D_MODEL);
    __syncthreads();
    float d0 = v0 - mu, d1 = v1 - mu;
    sh[tid] = d0 * d0 + d1 * d1; __syncthreads();
    for (int st = 128; st > 0; st >>= 1) {
        if (tid < st) sh[tid] += sh[tid + st];
        __syncthreads();
    }
    float rstd = rsqrtf(sh[0] * (1.f / D_MODEL) + 1e-5f);
    xout[row * D_MODEL + tid]       = d0 * rstd * s[tid]       + b[tid];
    xout[row * D_MODEL + tid + 256] = d1 * rstd * s[tid + 256] + b[tid + 256];
}

extern "C" void kernel_launch(void* const* d_in, const int* in_sizes, int n_in,
                              void* d_out, int out_size) {
    const float* atoms_x  = (const float*)d_in[0];
    const float* pos      = (const float*)d_in[1];
    const int*   atoms    = (const int*)d_in[2];
    const int*   edge_index = (const int*)d_in[3];
    const int*   edge_attr_types = (const int*)d_in[4];
    const int*   spatial_pos = (const int*)d_in[5];
    const int*   edge_input  = (const int*)d_in[6];
    const float* atom_tab   = (const float*)d_in[7];
    const float* degree_tab = (const float*)d_in[8];
    const float* w3d        = (const float*)d_in[9];
    const float* spd_tab    = (const float*)d_in[10];
    const float* edge_tab   = (const float*)d_in[11];
    const float* edge_dis   = (const float*)d_in[12];
    const float* means      = (const float*)d_in[13];
    const float* stds       = (const float*)d_in[14];
    const float* gamma_tab  = (const float*)d_in[15];
    const float* beta_tab   = (const float*)d_in[16];
    const float* pW1        = (const float*)d_in[17];
    const float* pW2        = (const float*)d_in[18];
    const float* cls        = (const float*)d_in[19];
    const float* Qw         = (const float*)d_in[20];
    const float* Kw         = (const float*)d_in[21];
    const float* Vw         = (const float*)d_in[22];
    const float* Wout       = (const float*)d_in[23];
    const float* F1         = (const float*)d_in[24];
    const float* F2         = (const float*)d_in[25];
    const float* ln1_s      = (const float*)d_in[26];
    const float* ln1_b      = (const float*)d_in[27];
    const float* ln2_s      = (const float*)d_in[28];
    const float* ln2_b      = (const float*)d_in[29];
    float* out = (float*)d_out;

    float *S, *x, *q, *k, *v, *o, *attn, *z, *h1, *bias;
    int *et;
    cudaGetSymbolAddress((void**)&S,    g_S);
    cudaGetSymbolAddress((void**)&bias, g_bias);
    cudaGetSymbolAddress((void**)&x,    g_x);
    cudaGetSymbolAddress((void**)&q,    g_q);
    cudaGetSymbolAddress((void**)&k,    g_k);
    cudaGetSymbolAddress((void**)&v,    g_v);
    cudaGetSymbolAddress((void**)&o,    g_o);
    cudaGetSymbolAddress((void**)&attn, g_attn);
    cudaGetSymbolAddress((void**)&z,    g_z);
    cudaGetSymbolAddress((void**)&h1,   g_h1);
    cudaGetSymbolAddress((void**)&et,   g_et);

    cudaFuncSetAttribute(fused_bias_kernel,
                         cudaFuncAttributeMaxDynamicSharedMemorySize, FUSED_SMEM);

    const float scaling = 0.17677669529663687f;

    zero_int_kernel<<<(NCELL + 255) / 256, 256>>>(et, NCELL);
    scatter_kernel<<<1, 1>>>(edge_index, edge_attr_types, 2048);
    degree_kernel<<<N_ATOM, 256>>>();
    zero_float_kernel<<<(N_ATOM * K_GAUSS + 255) / 256, 256>>>(S, N_ATOM * K_GAUSS);
    fused_bias_kernel<<<NCELL / 128, 256, FUSED_SMEM>>>(
        pos, gamma_tab, beta_tab, means, stds, pW1, pW2,
        spatial_pos, edge_input, spd_tab, edge_tab, edge_dis);
    xinit_kernel<<<N_ATOM, 256>>>(atoms_x, atoms, atom_tab, degree_tab, w3d, cls);

    for (int l = 0; l < N_LAYER; l++) {
        const float* Qwl = Qw + (size_t)l * HD * D_MODEL;
        const float* Kwl = Kw + (size_t)l * HD * D_MODEL;
        const float* Vwl = Vw + (size_t)l * HD * D_MODEL;
        const float* Woutl = Wout + (size_t)l * D_MODEL * HD;
        const float* F1l = F1 + (size_t)l * D_MODEL * D_MODEL;
        const float* F2l = F2 + (size_t)l * D_MODEL * D_MODEL;

        mma_gemm<128, 128, 0, 0, false, true><<<dim3(HD / 128, 5, 1), 256>>>(
            x, Qwl, q, nullptr, NP1, HD, D_MODEL, D_MODEL, D_MODEL, HD, 0, 0, 0, 0, 1.f);
        mma_gemm<128, 128, 0, 0, false, true><<<dim3(HD / 128, 5, 1), 256>>>(
            x, Kwl, k, nullptr, NP1, HD, D_MODEL, D_MODEL, D_MODEL, HD, 0, 0, 0, 0, 1.f);
        mma_gemm<128, 128, 0, 0, false, true><<<dim3(HD / 128, 5, 1), 256>>>(
            x, Vwl, v, nullptr, NP1, HD, D_MODEL, D_MODEL, D_MODEL, HD, 0, 0, 0, 0, 1.f);

        mma_gemm<128, 128, 2, 0, false, true><<<dim3(5, 5, N_HEAD), 256>>>(
            q, k, attn, bias, NP1, NP1, D_MODEL, HD, HD, NPAD,
            D_MODEL, D_MODEL, (long)NP1 * NPAD, (long)NCELL, scaling);

        softmax_kernel<<<N_HEAD * NP1, 256>>>();

        mma_gemm<128, 128, 0, 1, false, true><<<dim3(4, 5, N_HEAD), 256>>>(
            attn, v, o, nullptr, NP1, D_MODEL, NPAD, NPAD, HD, HD,
            (long)NP1 * NPAD, D_MODEL, D_MODEL, 0, 1.f);

        zero_float_kernel<<<(NP1 * D_MODEL + 255) / 256, 256>>>(z, NP1 * D_MODEL);
        mma_gemm<128, 128, 0, 0, true, true><<<dim3(4, 5, 16), 256>>>(
            o, Woutl, z, nullptr, NP1, D_MODEL, 512, HD, HD, D_MODEL,
            512, 512, 0, 0, 1.f);

        add_ln_kernel<<<NP1, 256>>>(x, z, ln1_s + l * D_MODEL, ln1_b + l * D_MODEL, x);

        mma_gemm<64, 64, 1, 0, false, true><<<dim3(8, 9, 1), 256>>>(
            x, F1l, h1, nullptr, NP1, D_MODEL, D_MODEL, D_MODEL, D_MODEL, D_MODEL,
            0, 0, 0, 0, 1.f);
        mma_gemm<64, 64, 0, 0, false, true><<<dim3(8, 9, 1), 256>>>(
            h1, F2l, z, nullptr, NP1, D_MODEL, D_MODEL, D_MODEL, D_MODEL, D_MODEL,
            0, 0, 0, 0, 1.f);

        float* lnout = (l == N_LAYER - 1) ? out : x;
        add_ln_kernel<<<NP1, 256>>>(x, z, ln2_s + l * D_MODEL, ln2_b + l * D_MODEL, lnout);
    }
}

// round 14
// speedup vs baseline: 1.0001x; 1.0001x over previous
#include <cuda_runtime.h>
#include <cuda_fp16.h>
#include <math.h>
#include <stdint.h>

#define N_ATOM 512
#define D_MODEL 512
#define N_HEAD 16
#define K_GAUSS 128
#define N_LAYER 4
#define NP1 513
#define NPAD 528
#define HD (N_HEAD * D_MODEL)
#define NCELL (N_ATOM * N_ATOM)

__device__ float g_S[N_ATOM * K_GAUSS];
__device__ float g_bias[(size_t)N_HEAD * NCELL];
__device__ int   g_et[NCELL];
__device__ int   g_deg[N_ATOM];
__device__ float g_x[NP1 * D_MODEL];
__device__ float g_q[(size_t)NP1 * HD];
__device__ float g_k[(size_t)NP1 * HD];
__device__ float g_v[(size_t)NPAD * HD];   // rows 513..527 stay zero
__device__ float g_o[(size_t)NP1 * HD];
__device__ float g_attn[(size_t)N_HEAD * NP1 * NPAD];
__device__ float g_z[NP1 * D_MODEL];
__device__ float g_h1[NP1 * D_MODEL];

__global__ void zero_int_kernel(int* p, int n) {
    int i = blockIdx.x * blockDim.x + threadIdx.x;
    if (i < n) p[i] = 0;
}
__global__ void zero_float_kernel(float* p, int n) {
    int i = blockIdx.x * blockDim.x + threadIdx.x;
    if (i < n) p[i] = 0.f;
}

__global__ void scatter_kernel(const int* __restrict__ edge_index,
                               const int* __restrict__ types, int E_) {
    if (blockIdx.x == 0 && threadIdx.x == 0) {
        for (int e = 0; e < E_; e++)
            g_et[edge_index[e] * N_ATOM + edge_index[E_ + e]] = types[e];
        for (int e = 0; e < E_; e++)
            g_et[edge_index[E_ + e] * N_ATOM + edge_index[e]] = types[e];
    }
}

__global__ void degree_kernel() {
    int i = blockIdx.x;
    int c = 0;
    for (int j = threadIdx.x; j < N_ATOM; j += 256)
        c += (g_et[i * N_ATOM + j] != 0);
    __shared__ int sh[256];
    sh[threadIdx.x] = c;
    __syncthreads();
    for (int s = 128; s > 0; s >>= 1) {
        if (threadIdx.x < s) sh[threadIdx.x] += sh[threadIdx.x + s];
        __syncthreads();
    }
    if (threadIdx.x == 0) g_deg[i] = sh[0];
}

#define MMAF16(d, a, b) asm volatile( \
    "mma.sync.aligned.m16n8k16.row.col.f32.f16.f16.f32 " \
    "{%0,%1,%2,%3},{%4,%5,%6,%7},{%8,%9},{%0,%1,%2,%3};\n" \
    : "+f"(d[0]), "+f"(d[1]), "+f"(d[2]), "+f"(d[3]) \
    : "r"(a[0]), "r"(a[1]), "r"(a[2]), "r"(a[3]), "r"(b[0]), "r"(b[1]))

#define LDSM_X4(r0, r1, r2, r3, addr) asm volatile( \
    "ldmatrix.sync.aligned.m8n8.x4.shared.b16 {%0,%1,%2,%3}, [%4];\n" \
    : "=r"(r0), "=r"(r1), "=r"(r2), "=r"(r3) : "r"(addr))

__device__ __forceinline__ uint32_t s2u(const void* p) {
    return (uint32_t)__cvta_generic_to_shared(p);
}

__device__ __forceinline__ void cvt_split2(__half* hi, __half* lo, float x0, float x1) {
    __half h0 = __float2half_rn(x0);
    __half h1 = __float2half_rn(x1);
    *(__half2*)hi = __halves2half2(h0, h1);
    *(__half2*)lo = __halves2half2(__float2half_rn(x0 - __half2float(h0)),
                                   __float2half_rn(x1 - __half2float(h1)));
}

// ---- fused preprocessing: psi on-the-fly -> MMA(pW1) -> gelu -> @pW2 + spd + edge
#define FUSED_SMEM 88576

__global__ __launch_bounds__(256) void fused_bias_kernel(
    const float* __restrict__ pos,
    const float* __restrict__ gamma_tab, const float* __restrict__ beta_tab,
    const float* __restrict__ means, const float* __restrict__ stds,
    const float* __restrict__ pW1, const float* __restrict__ pW2,
    const int* __restrict__ spatial_pos, const int* __restrict__ edge_input,
    const float* __restrict__ spd_tab, const float* __restrict__ edge_tab,
    const float* __restrict__ edge_dis)
{
    extern __shared__ char dyn[];
    float* means_s = (float*)dyn;
    float* isd_s   = means_s + 128;
    float* normc_s = isd_s + 128;
    float* xg_s    = normc_s + 128;
    float* S_s     = xg_s + 128;
    float* etab_s  = S_s + 128;
    float* pw2_s   = etab_s + 512;
    float* ew_s    = pw2_s + 2048;
    char*  scratch = (char*)(ew_s + 2048);
    __half* stA_hi = (__half*)scratch;
    __half* stA_lo = stA_hi + 6144;
    __half* stB_hi = stA_lo + 6144;
    __half* stB_lo = stB_hi + 6144;
    float*  Tsm    = (float*)scratch;

    int tid = threadIdx.x;
    long cell0 = (long)blockIdx.x * 128;
    int i_row = (int)(cell0 >> 9);

    if (tid < 128) {
        float sd = fabsf(stds[tid]) + 0.01f;
        means_s[tid] = means[tid];
        isd_s[tid] = 1.f / sd;
        normc_s[tid] = 0.3989422804014327f / sd;
        S_s[tid] = 0.f;
        int j = (int)(cell0 & 511) + tid;
        float dx = pos[i_row * 3 + 0] - pos[j * 3 + 0];
        float dy = pos[i_row * 3 + 1] - pos[j * 3 + 1];
        float dz = pos[i_row * 3 + 2] - pos[j * 3 + 2];
        float dist = sqrtf(dx * dx + dy * dy + dz * dz + 1e-12f);
        int t = g_et[cell0 + tid];
        xg_s[tid] = gamma_tab[t] * dist + beta_tab[t];
    }
    for (int i2 = tid; i2 < 512; i2 += 256) etab_s[i2] = edge_tab[i2];
    for (int i2 = tid; i2 < 2048; i2 += 256) pw2_s[i2] = pW2[i2];
    for (int i2 = tid; i2 < 2048; i2 += 256) ew_s[i2] = edge_dis[i2];
    __syncthreads();

    int wid = tid >> 5, lane = tid & 31;
    int wm = wid >> 2, wn = wid & 3;
    int g = lane >> 2, tg = lane & 3;

    float acc[4][4][4];
    #pragma unroll
    for (int a = 0; a < 4; a++)
        #pragma unroll
        for (int b = 0; b < 4; b++)
            #pragma unroll
            for (int t = 0; t < 4; t++) acc[a][b][t] = 0.f;

    float4 ra[2], rb[2];

    auto computeA = [&](int c) {
        int k0 = c * 16;
        #pragma unroll
        for (int it = 0; it < 2; it++) {
            int idx = it * 256 + tid;
            int r = idx >> 2, c4 = idx & 3;
            float xgr = xg_s[r];
            float e[4];
            #pragma unroll
            for (int q = 0; q < 4; q++) {
                int kk = k0 + c4 * 4 + q;
                float u = (xgr - means_s[kk]) * isd_s[kk];
                e[q] = normc_s[kk] * expf(-0.5f * u * u);
            }
            ra[it] = make_float4(e[0], e[1], e[2], e[3]);
        }
        float p0 = ra[0].x + ra[1].x, p1 = ra[0].y + ra[1].y;
        float p2 = ra[0].z + ra[1].z, p3 = ra[0].w + ra[1].w;
        #pragma unroll
        for (int m = 4; m <= 16; m <<= 1) {
            p0 += __shfl_xor_sync(0xffffffffu, p0, m);
            p1 += __shfl_xor_sync(0xffffffffu, p1, m);
            p2 += __shfl_xor_sync(0xffffffffu, p2, m);
            p3 += __shfl_xor_sync(0xffffffffu, p3, m);
        }
        if (lane < 4) {
            atomicAdd(&S_s[k0 + lane * 4 + 0], p0);
            atomicAdd(&S_s[k0 + lane * 4 + 1], p1);
            atomicAdd(&S_s[k0 + lane * 4 + 2], p2);
            atomicAdd(&S_s[k0 + lane * 4 + 3], p3);
        }
    };
    auto loadB = [&](int c) {
        int k0 = c * 16;
        #pragma unroll
        for (int it = 0; it < 2; it++) {
            int idx = it * 256 + tid;
            int r = idx >> 2, c4 = idx & 3;
            rb[it] = *(const float4*)(pW1 + r * 128 + k0 + c4 * 4);
        }
    };
    auto storeAB = [&](int st) {
        #pragma unroll
        for (int it = 0; it < 2; it++) {
            int idx = it * 256 + tid;
            int r = idx >> 2, c4 = idx & 3;
            __half* pah = stA_hi + st * 3072 + r * 24 + c4 * 4;
            __half* pal = stA_lo + st * 3072 + r * 24 + c4 * 4;
            cvt_split2(pah, pal, ra[it].x, ra[it].y);
            cvt_split2(pah + 2, pal + 2, ra[it].z, ra[it].w);
            __half* pbh = stB_hi + st * 3072 + r * 24 + c4 * 4;
            __half* pbl = stB_lo + st * 3072 + r * 24 + c4 * 4;
            cvt_split2(pbh, pbl, rb[it].x, rb[it].y);
            cvt_split2(pbh + 2, pbl + 2, rb[it].z, rb[it].w);
        }
    };

    computeA(0); loadB(0); storeAB(0);
    for (int c = 0; c < 8; c++) {
        __syncthreads();
        int st = c & 1;
        if (c < 7) { computeA(c + 1); loadB(c + 1); }
        uint32_t ah[4][4], al[4][4], bh[4][2], bl[4][2];
        #pragma unroll
        for (int mt = 0; mt < 4; mt++) {
            int row = wm * 64 + mt * 16 + (lane & 15);
            int colb = (lane >> 4) << 3;
            uint32_t ad = s2u(stA_hi + st * 3072 + row * 24 + colb);
            LDSM_X4(ah[mt][0], ah[mt][1], ah[mt][2], ah[mt][3], ad);
            ad = s2u(stA_lo + st * 3072 + row * 24 + colb);
            LDSM_X4(al[mt][0], al[mt][1], al[mt][2], al[mt][3], ad);
        }
        #pragma unroll
        for (int np = 0; np < 2; np++) {
            int brow = wn * 32 + np * 16 + (lane & 7) + ((lane >> 4) << 3);
            int bcol = ((lane >> 3) & 1) * 8;
            uint32_t bd = s2u(stB_hi + st * 3072 + brow * 24 + bcol);
            LDSM_X4(bh[2 * np][0], bh[2 * np][1], bh[2 * np + 1][0], bh[2 * np + 1][1], bd);
            bd = s2u(stB_lo + st * 3072 + brow * 24 + bcol);
            LDSM_X4(bl[2 * np][0], bl[2 * np][1], bl[2 * np + 1][0], bl[2 * np + 1][1], bd);
        }
        #pragma unroll
        for (int mt = 0; mt < 4; mt++)
            #pragma unroll
            for (int nt = 0; nt < 4; nt++) {
                MMAF16(acc[mt][nt], ah[mt], bh[nt]);
                MMAF16(acc[mt][nt], ah[mt], bl[nt]);
                MMAF16(acc[mt][nt], al[mt], bh[nt]);
            }
        if (c < 7) storeAB((c + 1) & 1);
    }
    __syncthreads();

    #pragma unroll
    for (int mt = 0; mt < 4; mt++)
        #pragma unroll
        for (int nt = 0; nt < 4; nt++)
            #pragma unroll
            for (int t = 0; t < 4; t++) {
                int gm = wm * 64 + mt * 16 + g + ((t >= 2) ? 8 : 0);
                int gn = wn * 32 + nt * 8 + tg * 2 + (t & 1);
                float v = acc[mt][nt][t];
                Tsm[gm * 132 + gn] = 0.5f * v * (1.f + erff(v * 0.7071067811865476f));
            }
    __syncthreads();

    int h = tid >> 4;
    for (int it2 = 0; it2 < 8; it2++) {
        int cl = (tid & 15) + it2 * 16;
        long cellg = cell0 + cl;
        float a2 = 0.f;
        const float* trow = &Tsm[cl * 132];
        const float* prow = &pw2_s[h * 128];
        #pragma unroll 8
        for (int k2 = 0; k2 < 128; k2++) a2 += trow[k2] * prow[k2];
        int sp = spatial_pos[cellg];
        a2 += spd_tab[sp * 16 + h];
        float esum = 0.f;
        for (int m = 0; m < 8; m++) {
            int ei = edge_input[cellg * 8 + m];
            const float* ewm = &ew_s[m * 256];
            #pragma unroll
            for (int hh = 0; hh < 16; hh++)
                esum += etab_s[ei * 16 + hh] * ewm[hh * 16 + h];
        }
        float spf = (sp == 0) ? 1.f : (float)sp;
        g_bias[(size_t)h * NCELL + cellg] = a2 + esum / spf;
    }
    if (tid < 128) atomicAdd(&g_S[i_row * 128 + tid], S_s[tid]);
}

__global__ void xinit_kernel(const float* __restrict__ atoms_x,
                             const int* __restrict__ atoms,
                             const float* __restrict__ atom_tab,
                             const float* __restrict__ degree_tab,
                             const float* __restrict__ w3d,
                             const float* __restrict__ cls) {
    int i = blockIdx.x;
    __shared__ float Ssh[128];
    if (threadIdx.x < 128) Ssh[threadIdx.x] = g_S[i * K_GAUSS + threadIdx.x];
    __syncthreads();
    int a = atoms[i], dgi = g_deg[i];
    for (int d = threadIdx.x; d < D_MODEL; d += blockDim.x) {
        float acc = 0.f;
        const float* wrow = w3d + (size_t)d * K_GAUSS;
        #pragma unroll 8
        for (int k = 0; k < 128; k++) acc += Ssh[k] * wrow[k];
        g_x[(i + 1) * D_MODEL + d] = atoms_x[i * D_MODEL + d]
                                   + atom_tab[a * D_MODEL + d]
                                   + degree_tab[dgi * D_MODEL + d] + acc;
    }
    if (i == 0)
        for (int d = threadIdx.x; d < D_MODEL; d += blockDim.x)
            g_x[d] = cls[d];
}

// ---- fp16x3 GEMM, scalar smem fragment loads, double-buffered, 2 CTAs/SM ------
template <int BM, int BN, int EPI, int BLOAD, bool ATOMIC, bool VECA>
__global__ __launch_bounds__(256, 2) void mma_gemm(
    const float* __restrict__ Ag, const float* __restrict__ Bg,
    float* __restrict__ Cg, const float* __restrict__ biasg,
    int M, int N, int K, int lda, int ldb, int ldc,
    long strA, long strB, long strC, long strBias, float alpha) {

    constexpr int KC = 16;
    constexpr int KS = 24;
    constexpr int WM = BM / 2;
    constexpr int WN = BN / 4;
    constexpr int MT = WM / 16;
    constexpr int NT = WN / 8;
    constexpr int A4 = (BM * KC) / (4 * 256);
    constexpr int B4 = (BN * KC) / (4 * 256);
    constexpr int NB4 = BN / 4;

    __shared__ __align__(16) __half smA_hi[2][BM][KS];
    __shared__ __align__(16) __half smA_lo[2][BM][KS];
    __shared__ __align__(16) __half smB_hi[2][BN][KS];
    __shared__ __align__(16) __half smB_lo[2][BN][KS];

    int bz = blockIdx.z;
    const float* A = Ag + (long)bz * strA;
    const float* B = Bg + (long)bz * strB;
    float* C = Cg + (long)bz * strC;
    const float* bias = (EPI == 2) ? (biasg + (long)bz * strBias) : nullptr;

    int bm = blockIdx.y * BM;
    int bn = blockIdx.x * BN;
    int tid = threadIdx.x;
    int wid = tid >> 5, lane = tid & 31;
    int wm = wid >> 2, wn = wid & 3;
    int g = lane >> 2, tg = lane & 3;

    float acc[MT][NT][4];
    #pragma unroll
    for (int i = 0; i < MT; i++)
        #pragma unroll
        for (int j = 0; j < NT; j++)
            #pragma unroll
            for (int t = 0; t < 4; t++) acc[i][j][t] = 0.f;

    float4 ra[A4], rb[B4];
    int nc = (K + KC - 1) / KC;

    auto loadA = [&](int c) {
        int k0 = c * KC;
        #pragma unroll
        for (int it = 0; it < A4; it++) {
            int idx = it * 256 + tid;
            int r = idx >> 2, c4 = idx & 3;
            int gm = bm + r;
            if (VECA) {
                if (gm < M)
                    ra[it] = *(const float4*)(A + (long)gm * lda + k0 + c4 * 4);
                else
                    ra[it] = make_float4(0.f, 0.f, 0.f, 0.f);
            } else {
                float e[4];
                #pragma unroll
                for (int q2 = 0; q2 < 4; q2++) {
                    int gk = k0 + c4 * 4 + q2;
                    e[q2] = (gm < M && gk < K) ? A[(long)gm * lda + gk] : 0.f;
                }
                ra[it] = make_float4(e[0], e[1], e[2], e[3]);
            }
        }
    };
    auto loadB = [&](int c) {
        int k0 = c * KC;
        if (BLOAD == 0) {
            #pragma unroll
            for (int it = 0; it < B4; it++) {
                int idx = it * 256 + tid;
                int r = idx >> 2, c4 = idx & 3;
                int gn = bn + r;
                if (gn < N)
                    rb[it] = *(const float4*)(B + (long)gn * ldb + k0 + c4 * 4);
                else
                    rb[it] = make_float4(0.f, 0.f, 0.f, 0.f);
            }
        } else {
            #pragma unroll
            for (int it = 0; it < B4; it++) {
                int idx = it * 256 + tid;
                int kk = idx / NB4, n4 = idx % NB4;
                int gk = k0 + kk;
                if (gk < K)
                    rb[it] = *(const float4*)(B + (long)gk * ldb + bn + n4 * 4);
                else
                    rb[it] = make_float4(0.f, 0.f, 0.f, 0.f);
            }
        }
    };
    auto storeAB = [&](int st) {
        #pragma unroll
        for (int it = 0; it < A4; it++) {
            int idx = it * 256 + tid;
            int r = idx >> 2, c4 = idx & 3;
            cvt_split2(&smA_hi[st][r][c4 * 4], &smA_lo[st][r][c4 * 4], ra[it].x, ra[it].y);
            cvt_split2(&smA_hi[st][r][c4 * 4 + 2], &smA_lo[st][r][c4 * 4 + 2], ra[it].z, ra[it].w);
        }
        if (BLOAD == 0) {
            #pragma unroll
            for (int it = 0; it < B4; it++) {
                int idx = it * 256 + tid;
                int r = idx >> 2, c4 = idx & 3;
                cvt_split2(&smB_hi[st][r][c4 * 4], &smB_lo[st][r][c4 * 4], rb[it].x, rb[it].y);
                cvt_split2(&smB_hi[st][r][c4 * 4 + 2], &smB_lo[st][r][c4 * 4 + 2], rb[it].z, rb[it].w);
            }
        } else {
            #pragma unroll
            for (int it = 0; it < B4; it++) {
                int idx = it * 256 + tid;
                int kk = idx / NB4, n4 = idx % NB4;
                float e[4] = {rb[it].x, rb[it].y, rb[it].z, rb[it].w};
                #pragma unroll
                for (int q2 = 0; q2 < 4; q2++) {
                    __half hh = __float2half_rn(e[q2]);
                    smB_hi[st][n4 * 4 + q2][kk] = hh;
                    smB_lo[st][n4 * 4 + q2][kk] = __float2half_rn(e[q2] - __half2float(hh));
                }
            }
        }
    };

    loadA(0); loadB(0);
    storeAB(0);

    for (int c = 0; c < nc; c++) {
        __syncthreads();
        int st = c & 1;
        if (c + 1 < nc) { loadA(c + 1); loadB(c + 1); }

        uint32_t ah[MT][4], al[MT][4], bh[NT][2], bl[NT][2];
        int cc = tg * 2;
        #pragma unroll
        for (int mt = 0; mt < MT; mt++) {
            int row = wm * WM + mt * 16 + g;
            ah[mt][0] = *(const uint32_t*)&smA_hi[st][row][cc];
            ah[mt][1] = *(const uint32_t*)&smA_hi[st][row + 8][cc];
            ah[mt][2] = *(const uint32_t*)&smA_hi[st][row][cc + 8];
            ah[mt][3] = *(const uint32_t*)&smA_hi[st][row + 8][cc + 8];
            al[mt][0] = *(const uint32_t*)&smA_lo[st][row][cc];
            al[mt][1] = *(const uint32_t*)&smA_lo[st][row + 8][cc];
            al[mt][2] = *(const uint32_t*)&smA_lo[st][row][cc + 8];
            al[mt][3] = *(const uint32_t*)&smA_lo[st][row + 8][cc + 8];
        }
        #pragma unroll
        for (int nt = 0; nt < NT; nt++) {
            int col = wn * WN + nt * 8 + g;
            bh[nt][0] = *(const uint32_t*)&smB_hi[st][col][cc];
            bh[nt][1] = *(const uint32_t*)&smB_hi[st][col][cc + 8];
            bl[nt][0] = *(const uint32_t*)&smB_lo[st][col][cc];
            bl[nt][1] = *(const uint32_t*)&smB_lo[st][col][cc + 8];
        }
        #pragma unroll
        for (int mt = 0; mt < MT; mt++)
            #pragma unroll
            for (int nt = 0; nt < NT; nt++) {
                MMAF16(acc[mt][nt], ah[mt], bh[nt]);
                MMAF16(acc[mt][nt], ah[mt], bl[nt]);
                MMAF16(acc[mt][nt], al[mt], bh[nt]);
            }

        if (c + 1 < nc) storeAB((c + 1) & 1);
    }

    #pragma unroll
    for (int mt = 0; mt < MT; mt++) {
        #pragma unroll
        for (int nt = 0; nt < NT; nt++) {
            int r0 = bm + wm * WM + mt * 16 + g;
            int c0 = bn + wn * WN + nt * 8 + tg * 2;
            #pragma unroll
            for (int t = 0; t < 4; t++) {
                int gm = r0 + (t >= 2 ? 8 : 0);
                int gn = c0 + (t & 1);
                if (gm >= M || gn >= N) continue;
                float vv = acc[mt][nt][t] * alpha;
                if (EPI == 1) {
                    vv = 0.5f * vv * (1.f + erff(vv * 0.7071067811865476f));
                } else if (EPI == 2) {
                    if (gm >= 1 && gn >= 1)
                        vv += bias[(long)(gm - 1) * N_ATOM + (gn - 1)];
                }
                if (ATOMIC) atomicAdd(&C[(long)gm * ldc + gn], vv);
                else C[(long)gm * ldc + gn] = vv;
            }
        }
    }
}

__global__ void softmax_kernel() {
    long row = blockIdx.x;
    float* p = g_attn + row * NPAD;
    int tid = threadIdx.x;
    __shared__ float sh[256];
    float mx = -1e30f;
    for (int m = tid; m < NP1; m += 256) mx = fmaxf(mx, p[m]);
    sh[tid] = mx; __syncthreads();
    for (int s = 128; s > 0; s >>= 1) {
        if (tid < s) sh[tid] = fmaxf(sh[tid], sh[tid + s]);
        __syncthreads();
    }
    mx = sh[0]; __syncthreads();
    float sum = 0.f;
    for (int m = tid; m < NP1; m += 256) {
        float e = expf(p[m] - mx);
        p[m] = e;
        sum += e;
    }
    sh[tid] = sum; __syncthreads();
    for (int s = 128; s > 0; s >>= 1) {
        if (tid < s) sh[tid] += sh[tid + s];
        __syncthreads();
    }
    float inv = 1.f / sh[0];
    __syncthreads();
    for (int m = tid; m < NP1; m += 256) p[m] *= inv;
    if (tid < NPAD - NP1) p[NP1 + tid] = 0.f;
}

__global__ void add_ln_kernel(const float* __restrict__ xin, const float* __restrict__ z,
                              const float* __restrict__ s, const float* __restrict__ b,
                              float* __restrict__ xout) {
    int row = blockIdx.x, tid = threadIdx.x;
    float v0 = xin[row * D_MODEL + tid] + z[row * D_MODEL + tid];
    float v1 = xin[row * D_MODEL + tid + 256] + z[row * D_MODEL + tid + 256];
    __shared__ float sh[256];
    sh[tid] = v0 + v1; __syncthreads();
    for (int st = 128; st > 0; st >>= 1) {
        if (tid < st) sh[tid] += sh[tid + st];
        __syncthreads();
    }
    float mu = sh[0] * (1.f / D_MODEL);
    __syncthreads();
    float d0 = v0 - mu, d1 = v1 - mu;
    sh[tid] = d0 * d0 + d1 * d1; __syncthreads();
    for (int st = 128; st > 0; st >>= 1) {
        if (tid < st) sh[tid] += sh[tid + st];
        __syncthreads();
    }
    float rstd = rsqrtf(sh[0] * (1.f / D_MODEL) + 1e-5f);
    xout[row * D_MODEL + tid]       = d0 * rstd * s[tid]       + b[tid];
    xout[row * D_MODEL + tid + 256] = d1 * rstd * s[tid + 256] + b[tid + 256];
}

extern "C" void kernel_launch(void* const* d_in, const int* in_sizes, int n_in,
                              void* d_out, int out_size) {
    const float* atoms_x  = (const float*)d_in[0];
    const float* pos      = (const float*)d_in[1];
    const int*   atoms    = (const int*)d_in[2];
    const int*   edge_index = (const int*)d_in[3];
    const int*   edge_attr_types = (const int*)d_in[4];
    const int*   spatial_pos = (const int*)d_in[5];
    const int*   edge_input  = (const int*)d_in[6];
    const float* atom_tab   = (const float*)d_in[7];
    const float* degree_tab = (const float*)d_in[8];
    const float* w3d        = (const float*)d_in[9];
    const float* spd_tab    = (const float*)d_in[10];
    const float* edge_tab   = (const float*)d_in[11];
    const float* edge_dis   = (const float*)d_in[12];
    const float* means      = (const float*)d_in[13];
    const float* stds       = (const float*)d_in[14];
    const float* gamma_tab  = (const float*)d_in[15];
    const float* beta_tab   = (const float*)d_in[16];
    const float* pW1        = (const float*)d_in[17];
    const float* pW2        = (const float*)d_in[18];
    const float* cls        = (const float*)d_in[19];
    const float* Qw         = (const float*)d_in[20];
    const float* Kw         = (const float*)d_in[21];
    const float* Vw         = (const float*)d_in[22];
    const float* Wout       = (const float*)d_in[23];
    const float* F1         = (const float*)d_in[24];
    const float* F2         = (const float*)d_in[25];
    const float* ln1_s      = (const float*)d_in[26];
    const float* ln1_b      = (const float*)d_in[27];
    const float* ln2_s      = (const float*)d_in[28];
    const float* ln2_b      = (const float*)d_in[29];
    float* out = (float*)d_out;

    float *S, *x, *q, *k, *v, *o, *attn, *z, *h1, *bias;
    int *et;
    cudaGetSymbolAddress((void**)&S,    g_S);
    cudaGetSymbolAddress((void**)&bias, g_bias);
    cudaGetSymbolAddress((void**)&x,    g_x);
    cudaGetSymbolAddress((void**)&q,    g_q);
    cudaGetSymbolAddress((void**)&k,    g_k);
    cudaGetSymbolAddress((void**)&v,    g_v);
    cudaGetSymbolAddress((void**)&o,    g_o);
    cudaGetSymbolAddress((void**)&attn, g_attn);
    cudaGetSymbolAddress((void**)&z,    g_z);
    cudaGetSymbolAddress((void**)&h1,   g_h1);
    cudaGetSymbolAddress((void**)&et,   g_et);

    cudaFuncSetAttribute(fused_bias_kernel,
                         cudaFuncAttributeMaxDynamicSharedMemorySize, FUSED_SMEM);

    const float scaling = 0.17677669529663687f;

    zero_int_kernel<<<(NCELL + 255) / 256, 256>>>(et, NCELL);
    scatter_kernel<<<1, 1>>>(edge_index, edge_attr_types, 2048);
    degree_kernel<<<N_ATOM, 256>>>();
    zero_float_kernel<<<(N_ATOM * K_GAUSS + 255) / 256, 256>>>(S, N_ATOM * K_GAUSS);
    fused_bias_kernel<<<NCELL / 128, 256, FUSED_SMEM>>>(
        pos, gamma_tab, beta_tab, means, stds, pW1, pW2,
        spatial_pos, edge_input, spd_tab, edge_tab, edge_dis);
    xinit_kernel<<<N_ATOM, 256>>>(atoms_x, atoms, atom_tab, degree_tab, w3d, cls);

    for (int l = 0; l < N_LAYER; l++) {
        const float* Qwl = Qw + (size_t)l * HD * D_MODEL;
        const float* Kwl = Kw + (size_t)l * HD * D_MODEL;
        const float* Vwl = Vw + (size_t)l * HD * D_MODEL;
        const float* Woutl = Wout + (size_t)l * D_MODEL * HD;
        const float* F1l = F1 + (size_t)l * D_MODEL * D_MODEL;
        const float* F2l = F2 + (size_t)l * D_MODEL * D_MODEL;

        mma_gemm<128, 128, 0, 0, false, true><<<dim3(HD / 128, 5, 1), 256>>>(
            x, Qwl, q, nullptr, NP1, HD, D_MODEL, D_MODEL, D_MODEL, HD, 0, 0, 0, 0, 1.f);
        mma_gemm<128, 128, 0, 0, false, true><<<dim3(HD / 128, 5, 1), 256>>>(
            x, Kwl, k, nullptr, NP1, HD, D_MODEL, D_MODEL, D_MODEL, HD, 0, 0, 0, 0, 1.f);
        mma_gemm<128, 128, 0, 0, false, true><<<dim3(HD / 128, 5, 1), 256>>>(
            x, Vwl, v, nullptr, NP1, HD, D_MODEL, D_MODEL, D_MODEL, HD, 0, 0, 0, 0, 1.f);

        mma_gemm<128, 128, 2, 0, false, true><<<dim3(5, 5, N_HEAD), 256>>>(
            q, k, attn, bias, NP1, NP1, D_MODEL, HD, HD, NPAD,
            D_MODEL, D_MODEL, (long)NP1 * NPAD, (long)NCELL, scaling);

        softmax_kernel<<<N_HEAD * NP1, 256>>>();

        mma_gemm<128, 128, 0, 1, false, true><<<dim3(4, 5, N_HEAD), 256>>>(
            attn, v, o, nullptr, NP1, D_MODEL, NPAD, NPAD, HD, HD,
            (long)NP1 * NPAD, D_MODEL, D_MODEL, 0, 1.f);

        zero_float_kernel<<<(NP1 * D_MODEL + 255) / 256, 256>>>(z, NP1 * D_MODEL);
        mma_gemm<128, 128, 0, 0, true, true><<<dim3(4, 5, 16), 256>>>(
            o, Woutl, z, nullptr, NP1, D_MODEL, 512, HD, HD, D_MODEL,
            512, 512, 0, 0, 1.f);

        add_ln_kernel<<<NP1, 256>>>(x, z, ln1_s + l * D_MODEL, ln1_b + l * D_MODEL, x);

        mma_gemm<64, 64, 1, 0, false, true><<<dim3(8, 9, 1), 256>>>(
            x, F1l, h1, nullptr, NP1, D_MODEL, D_MODEL, D_MODEL, D_MODEL, D_MODEL,
            0, 0, 0, 0, 1.f);
        mma_gemm<64, 64, 0, 0, false, true><<<dim3(8, 9, 1), 256>>>(
            h1, F2l, z, nullptr, NP1, D_MODEL, D_MODEL, D_MODEL, D_MODEL, D_MODEL,
            0, 0, 0, 0, 1.f);

        float* lnout = (l == N_LAYER - 1) ? out : x;
        add_ln_kernel<<<NP1, 256>>>(x, z, ln2_s + l * D_MODEL, ln2_b + l * D_MODEL, lnout);
    }
}

// round 15
// speedup vs baseline: 1.0028x; 1.0027x over previous
#include <cuda_runtime.h>
#include <cuda_fp16.h>
#include <math.h>
#include <stdint.h>

#define N_ATOM 512
#define D_MODEL 512
#define N_HEAD 16
#define K_GAUSS 128
#define N_LAYER 4
#define NP1 513
#define NPAD 528
#define HD (N_HEAD * D_MODEL)
#define NCELL (N_ATOM * N_ATOM)

__device__ float g_S[N_ATOM * K_GAUSS];
__device__ float g_bias[(size_t)N_HEAD * NCELL];
__device__ int   g_et[NCELL];
__device__ int   g_deg[N_ATOM];
__device__ float g_x[NP1 * D_MODEL];
__device__ float g_q[(size_t)NP1 * HD];
__device__ float g_k[(size_t)NP1 * HD];
__device__ float g_v[(size_t)NPAD * HD];   // rows 513..527 stay zero
__device__ float g_o[(size_t)NP1 * HD];
__device__ float g_attn[(size_t)N_HEAD * NP1 * NPAD];
__device__ float g_z[NP1 * D_MODEL];
__device__ float g_h1[NP1 * D_MODEL];

__global__ void zero_int_kernel(int* p, int n) {
    int i = blockIdx.x * blockDim.x + threadIdx.x;
    if (i < n) p[i] = 0;
}
__global__ void zero_float_kernel(float* p, int n) {
    int i = blockIdx.x * blockDim.x + threadIdx.x;
    if (i < n) p[i] = 0.f;
}

__global__ void scatter_kernel(const int* __restrict__ edge_index,
                               const int* __restrict__ types, int E_) {
    if (blockIdx.x == 0 && threadIdx.x == 0) {
        for (int e = 0; e < E_; e++)
            g_et[edge_index[e] * N_ATOM + edge_index[E_ + e]] = types[e];
        for (int e = 0; e < E_; e++)
            g_et[edge_index[E_ + e] * N_ATOM + edge_index[e]] = types[e];
    }
}

__global__ void degree_kernel() {
    int i = blockIdx.x;
    int c = 0;
    for (int j = threadIdx.x; j < N_ATOM; j += 256)
        c += (g_et[i * N_ATOM + j] != 0);
    __shared__ int sh[256];
    sh[threadIdx.x] = c;
    __syncthreads();
    for (int s = 128; s > 0; s >>= 1) {
        if (threadIdx.x < s) sh[threadIdx.x] += sh[threadIdx.x + s];
        __syncthreads();
    }
    if (threadIdx.x == 0) g_deg[i] = sh[0];
}

#define MMAF16(d, a, b) asm volatile( \
    "mma.sync.aligned.m16n8k16.row.col.f32.f16.f16.f32 " \
    "{%0,%1,%2,%3},{%4,%5,%6,%7},{%8,%9},{%0,%1,%2,%3};\n" \
    : "+f"(d[0]), "+f"(d[1]), "+f"(d[2]), "+f"(d[3]) \
    : "r"(a[0]), "r"(a[1]), "r"(a[2]), "r"(a[3]), "r"(b[0]), "r"(b[1]))

#define LDSM_X4(r0, r1, r2, r3, addr) asm volatile( \
    "ldmatrix.sync.aligned.m8n8.x4.shared.b16 {%0,%1,%2,%3}, [%4];\n" \
    : "=r"(r0), "=r"(r1), "=r"(r2), "=r"(r3) : "r"(addr))

__device__ __forceinline__ uint32_t s2u(const void* p) {
    return (uint32_t)__cvta_generic_to_shared(p);
}

__device__ __forceinline__ void cvt_split2(__half* hi, __half* lo, float x0, float x1) {
    __half h0 = __float2half_rn(x0);
    __half h1 = __float2half_rn(x1);
    *(__half2*)hi = __halves2half2(h0, h1);
    *(__half2*)lo = __halves2half2(__float2half_rn(x0 - __half2float(h0)),
                                   __float2half_rn(x1 - __half2float(h1)));
}

// ---- fused preprocessing: psi on-the-fly -> MMA(pW1) -> gelu -> @pW2 + spd + edge
#define FUSED_SMEM 88576

__global__ __launch_bounds__(256) void fused_bias_kernel(
    const float* __restrict__ pos,
    const float* __restrict__ gamma_tab, const float* __restrict__ beta_tab,
    const float* __restrict__ means, const float* __restrict__ stds,
    const float* __restrict__ pW1, const float* __restrict__ pW2,
    const int* __restrict__ spatial_pos, const int* __restrict__ edge_input,
    const float* __restrict__ spd_tab, const float* __restrict__ edge_tab,
    const float* __restrict__ edge_dis)
{
    extern __shared__ char dyn[];
    float* means_s = (float*)dyn;
    float* isd_s   = means_s + 128;
    float* normc_s = isd_s + 128;
    float* xg_s    = normc_s + 128;
    float* S_s     = xg_s + 128;
    float* etab_s  = S_s + 128;
    float* pw2_s   = etab_s + 512;
    float* ew_s    = pw2_s + 2048;
    char*  scratch = (char*)(ew_s + 2048);
    __half* stA_hi = (__half*)scratch;
    __half* stA_lo = stA_hi + 6144;
    __half* stB_hi = stA_lo + 6144;
    __half* stB_lo = stB_hi + 6144;
    float*  Tsm    = (float*)scratch;

    int tid = threadIdx.x;
    long cell0 = (long)blockIdx.x * 128;
    int i_row = (int)(cell0 >> 9);

    if (tid < 128) {
        float sd = fabsf(stds[tid]) + 0.01f;
        means_s[tid] = means[tid];
        isd_s[tid] = 1.f / sd;
        normc_s[tid] = 0.3989422804014327f / sd;
        S_s[tid] = 0.f;
        int j = (int)(cell0 & 511) + tid;
        float dx = pos[i_row * 3 + 0] - pos[j * 3 + 0];
        float dy = pos[i_row * 3 + 1] - pos[j * 3 + 1];
        float dz = pos[i_row * 3 + 2] - pos[j * 3 + 2];
        float dist = sqrtf(dx * dx + dy * dy + dz * dz + 1e-12f);
        int t = g_et[cell0 + tid];
        xg_s[tid] = gamma_tab[t] * dist + beta_tab[t];
    }
    for (int i2 = tid; i2 < 512; i2 += 256) etab_s[i2] = edge_tab[i2];
    for (int i2 = tid; i2 < 2048; i2 += 256) pw2_s[i2] = pW2[i2];
    for (int i2 = tid; i2 < 2048; i2 += 256) ew_s[i2] = edge_dis[i2];
    __syncthreads();

    int wid = tid >> 5, lane = tid & 31;
    int wm = wid >> 2, wn = wid & 3;
    int g = lane >> 2, tg = lane & 3;

    float acc[4][4][4];
    #pragma unroll
    for (int a = 0; a < 4; a++)
        #pragma unroll
        for (int b = 0; b < 4; b++)
            #pragma unroll
            for (int t = 0; t < 4; t++) acc[a][b][t] = 0.f;

    float4 ra[2], rb[2];

    auto computeA = [&](int c) {
        int k0 = c * 16;
        #pragma unroll
        for (int it = 0; it < 2; it++) {
            int idx = it * 256 + tid;
            int r = idx >> 2, c4 = idx & 3;
            float xgr = xg_s[r];
            float e[4];
            #pragma unroll
            for (int q = 0; q < 4; q++) {
                int kk = k0 + c4 * 4 + q;
                float u = (xgr - means_s[kk]) * isd_s[kk];
                e[q] = normc_s[kk] * expf(-0.5f * u * u);
            }
            ra[it] = make_float4(e[0], e[1], e[2], e[3]);
        }
        float p0 = ra[0].x + ra[1].x, p1 = ra[0].y + ra[1].y;
        float p2 = ra[0].z + ra[1].z, p3 = ra[0].w + ra[1].w;
        #pragma unroll
        for (int m = 4; m <= 16; m <<= 1) {
            p0 += __shfl_xor_sync(0xffffffffu, p0, m);
            p1 += __shfl_xor_sync(0xffffffffu, p1, m);
            p2 += __shfl_xor_sync(0xffffffffu, p2, m);
            p3 += __shfl_xor_sync(0xffffffffu, p3, m);
        }
        if (lane < 4) {
            atomicAdd(&S_s[k0 + lane * 4 + 0], p0);
            atomicAdd(&S_s[k0 + lane * 4 + 1], p1);
            atomicAdd(&S_s[k0 + lane * 4 + 2], p2);
            atomicAdd(&S_s[k0 + lane * 4 + 3], p3);
        }
    };
    auto loadB = [&](int c) {
        int k0 = c * 16;
        #pragma unroll
        for (int it = 0; it < 2; it++) {
            int idx = it * 256 + tid;
            int r = idx >> 2, c4 = idx & 3;
            rb[it] = *(const float4*)(pW1 + r * 128 + k0 + c4 * 4);
        }
    };
    auto storeAB = [&](int st) {
        #pragma unroll
        for (int it = 0; it < 2; it++) {
            int idx = it * 256 + tid;
            int r = idx >> 2, c4 = idx & 3;
            __half* pah = stA_hi + st * 3072 + r * 24 + c4 * 4;
            __half* pal = stA_lo + st * 3072 + r * 24 + c4 * 4;
            cvt_split2(pah, pal, ra[it].x, ra[it].y);
            cvt_split2(pah + 2, pal + 2, ra[it].z, ra[it].w);
            __half* pbh = stB_hi + st * 3072 + r * 24 + c4 * 4;
            __half* pbl = stB_lo + st * 3072 + r * 24 + c4 * 4;
            cvt_split2(pbh, pbl, rb[it].x, rb[it].y);
            cvt_split2(pbh + 2, pbl + 2, rb[it].z, rb[it].w);
        }
    };

    computeA(0); loadB(0); storeAB(0);
    for (int c = 0; c < 8; c++) {
        __syncthreads();
        int st = c & 1;
        if (c < 7) { computeA(c + 1); loadB(c + 1); }
        uint32_t ah[4][4], al[4][4], bh[4][2], bl[4][2];
        #pragma unroll
        for (int mt = 0; mt < 4; mt++) {
            int row = wm * 64 + mt * 16 + (lane & 15);
            int colb = (lane >> 4) << 3;
            uint32_t ad = s2u(stA_hi + st * 3072 + row * 24 + colb);
            LDSM_X4(ah[mt][0], ah[mt][1], ah[mt][2], ah[mt][3], ad);
            ad = s2u(stA_lo + st * 3072 + row * 24 + colb);
            LDSM_X4(al[mt][0], al[mt][1], al[mt][2], al[mt][3], ad);
        }
        #pragma unroll
        for (int np = 0; np < 2; np++) {
            int brow = wn * 32 + np * 16 + (lane & 7) + ((lane >> 4) << 3);
            int bcol = ((lane >> 3) & 1) * 8;
            uint32_t bd = s2u(stB_hi + st * 3072 + brow * 24 + bcol);
            LDSM_X4(bh[2 * np][0], bh[2 * np][1], bh[2 * np + 1][0], bh[2 * np + 1][1], bd);
            bd = s2u(stB_lo + st * 3072 + brow * 24 + bcol);
            LDSM_X4(bl[2 * np][0], bl[2 * np][1], bl[2 * np + 1][0], bl[2 * np + 1][1], bd);
        }
        #pragma unroll
        for (int mt = 0; mt < 4; mt++)
            #pragma unroll
            for (int nt = 0; nt < 4; nt++) {
                MMAF16(acc[mt][nt], ah[mt], bh[nt]);
                MMAF16(acc[mt][nt], ah[mt], bl[nt]);
                MMAF16(acc[mt][nt], al[mt], bh[nt]);
            }
        if (c < 7) storeAB((c + 1) & 1);
    }
    __syncthreads();

    #pragma unroll
    for (int mt = 0; mt < 4; mt++)
        #pragma unroll
        for (int nt = 0; nt < 4; nt++)
            #pragma unroll
            for (int t = 0; t < 4; t++) {
                int gm = wm * 64 + mt * 16 + g + ((t >= 2) ? 8 : 0);
                int gn = wn * 32 + nt * 8 + tg * 2 + (t & 1);
                float v = acc[mt][nt][t];
                Tsm[gm * 132 + gn] = 0.5f * v * (1.f + erff(v * 0.7071067811865476f));
            }
    __syncthreads();

    int h = tid >> 4;
    for (int it2 = 0; it2 < 8; it2++) {
        int cl = (tid & 15) + it2 * 16;
        long cellg = cell0 + cl;
        float a2 = 0.f;
        const float* trow = &Tsm[cl * 132];
        const float* prow = &pw2_s[h * 128];
        #pragma unroll 8
        for (int k2 = 0; k2 < 128; k2++) a2 += trow[k2] * prow[k2];
        int sp = spatial_pos[cellg];
        a2 += spd_tab[sp * 16 + h];
        float esum = 0.f;
        for (int m = 0; m < 8; m++) {
            int ei = edge_input[cellg * 8 + m];
            const float* ewm = &ew_s[m * 256];
            #pragma unroll
            for (int hh = 0; hh < 16; hh++)
                esum += etab_s[ei * 16 + hh] * ewm[hh * 16 + h];
        }
        float spf = (sp == 0) ? 1.f : (float)sp;
        g_bias[(size_t)h * NCELL + cellg] = a2 + esum / spf;
    }
    if (tid < 128) atomicAdd(&g_S[i_row * 128 + tid], S_s[tid]);
}

__global__ void xinit_kernel(const float* __restrict__ atoms_x,
                             const int* __restrict__ atoms,
                             const float* __restrict__ atom_tab,
                             const float* __restrict__ degree_tab,
                             const float* __restrict__ w3d,
                             const float* __restrict__ cls) {
    int i = blockIdx.x;
    __shared__ float Ssh[128];
    if (threadIdx.x < 128) Ssh[threadIdx.x] = g_S[i * K_GAUSS + threadIdx.x];
    __syncthreads();
    int a = atoms[i], dgi = g_deg[i];
    for (int d = threadIdx.x; d < D_MODEL; d += blockDim.x) {
        float acc = 0.f;
        const float* wrow = w3d + (size_t)d * K_GAUSS;
        #pragma unroll 8
        for (int k = 0; k < 128; k++) acc += Ssh[k] * wrow[k];
        g_x[(i + 1) * D_MODEL + d] = atoms_x[i * D_MODEL + d]
                                   + atom_tab[a * D_MODEL + d]
                                   + degree_tab[dgi * D_MODEL + d] + acc;
    }
    if (i == 0)
        for (int d = threadIdx.x; d < D_MODEL; d += blockDim.x)
            g_x[d] = cls[d];
}

// ---- fp16x3 GEMM, scalar smem fragment loads, double-buffered, 2 CTAs/SM ------
template <int BM, int BN, int EPI, int BLOAD, bool ATOMIC, bool VECA>
__global__ __launch_bounds__(256, 2) void mma_gemm(
    const float* __restrict__ Ag, const float* __restrict__ Bg,
    float* __restrict__ Cg, const float* __restrict__ biasg,
    int M, int N, int K, int lda, int ldb, int ldc,
    long strA, long strB, long strC, long strBias, float alpha) {

    constexpr int KC = 16;
    constexpr int KS = 24;
    constexpr int WM = BM / 2;
    constexpr int WN = BN / 4;
    constexpr int MT = WM / 16;
    constexpr int NT = WN / 8;
    constexpr int A4 = (BM * KC) / (4 * 256);
    constexpr int B4 = (BN * KC) / (4 * 256);
    constexpr int NB4 = BN / 4;

    __shared__ __align__(16) __half smA_hi[2][BM][KS];
    __shared__ __align__(16) __half smA_lo[2][BM][KS];
    __shared__ __align__(16) __half smB_hi[2][BN][KS];
    __shared__ __align__(16) __half smB_lo[2][BN][KS];

    int bz = blockIdx.z;
    const float* A = Ag + (long)bz * strA;
    const float* B = Bg + (long)bz * strB;
    float* C = Cg + (long)bz * strC;
    const float* bias = (EPI == 2) ? (biasg + (long)bz * strBias) : nullptr;

    int bm = blockIdx.y * BM;
    int bn = blockIdx.x * BN;
    int tid = threadIdx.x;
    int wid = tid >> 5, lane = tid & 31;
    int wm = wid >> 2, wn = wid & 3;
    int g = lane >> 2, tg = lane & 3;

    float acc[MT][NT][4];
    #pragma unroll
    for (int i = 0; i < MT; i++)
        #pragma unroll
        for (int j = 0; j < NT; j++)
            #pragma unroll
            for (int t = 0; t < 4; t++) acc[i][j][t] = 0.f;

    float4 ra[A4], rb[B4];
    int nc = (K + KC - 1) / KC;

    auto loadA = [&](int c) {
        int k0 = c * KC;
        #pragma unroll
        for (int it = 0; it < A4; it++) {
            int idx = it * 256 + tid;
            int r = idx >> 2, c4 = idx & 3;
            int gm = bm + r;
            if (VECA) {
                if (gm < M)
                    ra[it] = *(const float4*)(A + (long)gm * lda + k0 + c4 * 4);
                else
                    ra[it] = make_float4(0.f, 0.f, 0.f, 0.f);
            } else {
                float e[4];
                #pragma unroll
                for (int q2 = 0; q2 < 4; q2++) {
                    int gk = k0 + c4 * 4 + q2;
                    e[q2] = (gm < M && gk < K) ? A[(long)gm * lda + gk] : 0.f;
                }
                ra[it] = make_float4(e[0], e[1], e[2], e[3]);
            }
        }
    };
    auto loadB = [&](int c) {
        int k0 = c * KC;
        if (BLOAD == 0) {
            #pragma unroll
            for (int it = 0; it < B4; it++) {
                int idx = it * 256 + tid;
                int r = idx >> 2, c4 = idx & 3;
                int gn = bn + r;
                if (gn < N)
                    rb[it] = *(const float4*)(B + (long)gn * ldb + k0 + c4 * 4);
                else
                    rb[it] = make_float4(0.f, 0.f, 0.f, 0.f);
            }
        } else {
            #pragma unroll
            for (int it = 0; it < B4; it++) {
                int idx = it * 256 + tid;
                int kk = idx / NB4, n4 = idx % NB4;
                int gk = k0 + kk;
                if (gk < K)
                    rb[it] = *(const float4*)(B + (long)gk * ldb + bn + n4 * 4);
                else
                    rb[it] = make_float4(0.f, 0.f, 0.f, 0.f);
            }
        }
    };
    auto storeAB = [&](int st) {
        #pragma unroll
        for (int it = 0; it < A4; it++) {
            int idx = it * 256 + tid;
            int r = idx >> 2, c4 = idx & 3;
            cvt_split2(&smA_hi[st][r][c4 * 4], &smA_lo[st][r][c4 * 4], ra[it].x, ra[it].y);
            cvt_split2(&smA_hi[st][r][c4 * 4 + 2], &smA_lo[st][r][c4 * 4 + 2], ra[it].z, ra[it].w);
        }
        if (BLOAD == 0) {
            #pragma unroll
            for (int it = 0; it < B4; it++) {
                int idx = it * 256 + tid;
                int r = idx >> 2, c4 = idx & 3;
                cvt_split2(&smB_hi[st][r][c4 * 4], &smB_lo[st][r][c4 * 4], rb[it].x, rb[it].y);
                cvt_split2(&smB_hi[st][r][c4 * 4 + 2], &smB_lo[st][r][c4 * 4 + 2], rb[it].z, rb[it].w);
            }
        } else {
            #pragma unroll
            for (int it = 0; it < B4; it++) {
                int idx = it * 256 + tid;
                int kk = idx / NB4, n4 = idx % NB4;
                float e[4] = {rb[it].x, rb[it].y, rb[it].z, rb[it].w};
                #pragma unroll
                for (int q2 = 0; q2 < 4; q2++) {
                    __half hh = __float2half_rn(e[q2]);
                    smB_hi[st][n4 * 4 + q2][kk] = hh;
                    smB_lo[st][n4 * 4 + q2][kk] = __float2half_rn(e[q2] - __half2float(hh));
                }
            }
        }
    };

    loadA(0); loadB(0);
    storeAB(0);

    for (int c = 0; c < nc; c++) {
        __syncthreads();
        int st = c & 1;
        if (c + 1 < nc) { loadA(c + 1); loadB(c + 1); }

        uint32_t ah[MT][4], al[MT][4], bh[NT][2], bl[NT][2];
        int cc = tg * 2;
        #pragma unroll
        for (int mt = 0; mt < MT; mt++) {
            int row = wm * WM + mt * 16 + g;
            ah[mt][0] = *(const uint32_t*)&smA_hi[st][row][cc];
            ah[mt][1] = *(const uint32_t*)&smA_hi[st][row + 8][cc];
            ah[mt][2] = *(const uint32_t*)&smA_hi[st][row][cc + 8];
            ah[mt][3] = *(const uint32_t*)&smA_hi[st][row + 8][cc + 8];
            al[mt][0] = *(const uint32_t*)&smA_lo[st][row][cc];
            al[mt][1] = *(const uint32_t*)&smA_lo[st][row + 8][cc];
            al[mt][2] = *(const uint32_t*)&smA_lo[st][row][cc + 8];
            al[mt][3] = *(const uint32_t*)&smA_lo[st][row + 8][cc + 8];
        }
        #pragma unroll
        for (int nt = 0; nt < NT; nt++) {
            int col = wn * WN + nt * 8 + g;
            bh[nt][0] = *(const uint32_t*)&smB_hi[st][col][cc];
            bh[nt][1] = *(const uint32_t*)&smB_hi[st][col][cc + 8];
            bl[nt][0] = *(const uint32_t*)&smB_lo[st][col][cc];
            bl[nt][1] = *(const uint32_t*)&smB_lo[st][col][cc + 8];
        }
        #pragma unroll
        for (int mt = 0; mt < MT; mt++)
            #pragma unroll
            for (int nt = 0; nt < NT; nt++) {
                MMAF16(acc[mt][nt], ah[mt], bh[nt]);
                MMAF16(acc[mt][nt], ah[mt], bl[nt]);
                MMAF16(acc[mt][nt], al[mt], bh[nt]);
            }

        if (c + 1 < nc) storeAB((c + 1) & 1);
    }

    #pragma unroll
    for (int mt = 0; mt < MT; mt++) {
        #pragma unroll
        for (int nt = 0; nt < NT; nt++) {
            int r0 = bm + wm * WM + mt * 16 + g;
            int c0 = bn + wn * WN + nt * 8 + tg * 2;
            #pragma unroll
            for (int t = 0; t < 4; t++) {
                int gm = r0 + (t >= 2 ? 8 : 0);
                int gn = c0 + (t & 1);
                if (gm >= M || gn >= N) continue;
                float vv = acc[mt][nt][t] * alpha;
                if (EPI == 1) {
                    vv = 0.5f * vv * (1.f + erff(vv * 0.7071067811865476f));
                } else if (EPI == 2) {
                    if (gm >= 1 && gn >= 1)
                        vv += bias[(long)(gm - 1) * N_ATOM + (gn - 1)];
                }
                if (ATOMIC) atomicAdd(&C[(long)gm * ldc + gn], vv);
                else C[(long)gm * ldc + gn] = vv;
            }
        }
    }
}

__global__ void softmax_kernel() {
    long row = blockIdx.x;
    float* p = g_attn + row * NPAD;
    int tid = threadIdx.x;
    __shared__ float sh[256];
    float mx = -1e30f;
    for (int m = tid; m < NP1; m += 256) mx = fmaxf(mx, p[m]);
    sh[tid] = mx; __syncthreads();
    for (int s = 128; s > 0; s >>= 1) {
        if (tid < s) sh[tid] = fmaxf(sh[tid], sh[tid + s]);
        __syncthreads();
    }
    mx = sh[0]; __syncthreads();
    float sum = 0.f;
    for (int m = tid; m < NP1; m += 256) {
        float e = expf(p[m] - mx);
        p[m] = e;
        sum += e;
    }
    sh[tid] = sum; __syncthreads();
    for (int s = 128; s > 0; s >>= 1) {
        if (tid < s) sh[tid] += sh[tid + s];
        __syncthreads();
    }
    float inv = 1.f / sh[0];
    __syncthreads();
    for (int m = tid; m < NP1; m += 256) p[m] *= inv;
    if (tid < NPAD - NP1) p[NP1 + tid] = 0.f;
}

__global__ void add_ln_kernel(const float* __restrict__ xin, const float* __restrict__ z,
                              const float* __restrict__ s, const float* __restrict__ b,
                              float* __restrict__ xout) {
    int row = blockIdx.x, tid = threadIdx.x;
    float v0 = xin[row * D_MODEL + tid] + z[row * D_MODEL + tid];
    float v1 = xin[row * D_MODEL + tid + 256] + z[row * D_MODEL + tid + 256];
    __shared__ float sh[256];
    sh[tid] = v0 + v1; __syncthreads();
    for (int st = 128; st > 0; st >>= 1) {
        if (tid < st) sh[tid] += sh[tid + st];
        __syncthreads();
    }
    float mu = sh[0] * (1.f / D_MODEL);
    __syncthreads();
    float d0 = v0 - mu, d1 = v1 - mu;
    sh[tid] = d0 * d0 + d1 * d1; __syncthreads();
    for (int st = 128; st > 0; st >>= 1) {
        if (tid < st) sh[tid] += sh[tid + st];
        __syncthreads();
    }
    float rstd = rsqrtf(sh[0] * (1.f / D_MODEL) + 1e-5f);
    xout[row * D_MODEL + tid]       = d0 * rstd * s[tid]       + b[tid];
    xout[row * D_MODEL + tid + 256] = d1 * rstd * s[tid + 256] + b[tid + 256];
}

extern "C" void kernel_launch(void* const* d_in, const int* in_sizes, int n_in,
                              void* d_out, int out_size) {
    const float* atoms_x  = (const float*)d_in[0];
    const float* pos      = (const float*)d_in[1];
    const int*   atoms    = (const int*)d_in[2];
    const int*   edge_index = (const int*)d_in[3];
    const int*   edge_attr_types = (const int*)d_in[4];
    const int*   spatial_pos = (const int*)d_in[5];
    const int*   edge_input  = (const int*)d_in[6];
    const float* atom_tab   = (const float*)d_in[7];
    const float* degree_tab = (const float*)d_in[8];
    const float* w3d        = (const float*)d_in[9];
    const float* spd_tab    = (const float*)d_in[10];
    const float* edge_tab   = (const float*)d_in[11];
    const float* edge_dis   = (const float*)d_in[12];
    const float* means      = (const float*)d_in[13];
    const float* stds       = (const float*)d_in[14];
    const float* gamma_tab  = (const float*)d_in[15];
    const float* beta_tab   = (const float*)d_in[16];
    const float* pW1        = (const float*)d_in[17];
    const float* pW2        = (const float*)d_in[18];
    const float* cls        = (const float*)d_in[19];
    const float* Qw         = (const float*)d_in[20];
    const float* Kw         = (const float*)d_in[21];
    const float* Vw         = (const float*)d_in[22];
    const float* Wout       = (const float*)d_in[23];
    const float* F1         = (const float*)d_in[24];
    const float* F2         = (const float*)d_in[25];
    const float* ln1_s      = (const float*)d_in[26];
    const float* ln1_b      = (const float*)d_in[27];
    const float* ln2_s      = (const float*)d_in[28];
    const float* ln2_b      = (const float*)d_in[29];
    float* out = (float*)d_out;

    float *S, *x, *q, *k, *v, *o, *attn, *z, *h1, *bias;
    int *et;
    cudaGetSymbolAddress((void**)&S,    g_S);
    cudaGetSymbolAddress((void**)&bias, g_bias);
    cudaGetSymbolAddress((void**)&x,    g_x);
    cudaGetSymbolAddress((void**)&q,    g_q);
    cudaGetSymbolAddress((void**)&k,    g_k);
    cudaGetSymbolAddress((void**)&v,    g_v);
    cudaGetSymbolAddress((void**)&o,    g_o);
    cudaGetSymbolAddress((void**)&attn, g_attn);
    cudaGetSymbolAddress((void**)&z,    g_z);
    cudaGetSymbolAddress((void**)&h1,   g_h1);
    cudaGetSymbolAddress((void**)&et,   g_et);

    cudaFuncSetAttribute(fused_bias_kernel,
                         cudaFuncAttributeMaxDynamicSharedMemorySize, FUSED_SMEM);

    const float scaling = 0.17677669529663687f;

    zero_int_kernel<<<(NCELL + 255) / 256, 256>>>(et, NCELL);
    scatter_kernel<<<1, 1>>>(edge_index, edge_attr_types, 2048);
    degree_kernel<<<N_ATOM, 256>>>();
    zero_float_kernel<<<(N_ATOM * K_GAUSS + 255) / 256, 256>>>(S, N_ATOM * K_GAUSS);
    fused_bias_kernel<<<NCELL / 128, 256, FUSED_SMEM>>>(
        pos, gamma_tab, beta_tab, means, stds, pW1, pW2,
        spatial_pos, edge_input, spd_tab, edge_tab, edge_dis);
    xinit_kernel<<<N_ATOM, 256>>>(atoms_x, atoms, atom_tab, degree_tab, w3d, cls);

    for (int l = 0; l < N_LAYER; l++) {
        const float* Qwl = Qw + (size_t)l * HD * D_MODEL;
        const float* Kwl = Kw + (size_t)l * HD * D_MODEL;
        const float* Vwl = Vw + (size_t)l * HD * D_MODEL;
        const float* Woutl = Wout + (size_t)l * D_MODEL * HD;
        const float* F1l = F1 + (size_t)l * D_MODEL * D_MODEL;
        const float* F2l = F2 + (size_t)l * D_MODEL * D_MODEL;

        mma_gemm<128, 128, 0, 0, false, true><<<dim3(HD / 128, 5, 1), 256>>>(
            x, Qwl, q, nullptr, NP1, HD, D_MODEL, D_MODEL, D_MODEL, HD, 0, 0, 0, 0, 1.f);
        mma_gemm<128, 128, 0, 0, false, true><<<dim3(HD / 128, 5, 1), 256>>>(
            x, Kwl, k, nullptr, NP1, HD, D_MODEL, D_MODEL, D_MODEL, HD, 0, 0, 0, 0, 1.f);
        mma_gemm<128, 128, 0, 0, false, true><<<dim3(HD / 128, 5, 1), 256>>>(
            x, Vwl, v, nullptr, NP1, HD, D_MODEL, D_MODEL, D_MODEL, HD, 0, 0, 0, 0, 1.f);

        mma_gemm<128, 128, 2, 0, false, true><<<dim3(5, 5, N_HEAD), 256>>>(
            q, k, attn, bias, NP1, NP1, D_MODEL, HD, HD, NPAD,
            D_MODEL, D_MODEL, (long)NP1 * NPAD, (long)NCELL, scaling);

        softmax_kernel<<<N_HEAD * NP1, 256>>>();

        mma_gemm<128, 128, 0, 1, false, true><<<dim3(4, 5, N_HEAD), 256>>>(
            attn, v, o, nullptr, NP1, D_MODEL, NPAD, NPAD, HD, HD,
            (long)NP1 * NPAD, D_MODEL, D_MODEL, 0, 1.f);

        zero_float_kernel<<<(NP1 * D_MODEL + 255) / 256, 256>>>(z, NP1 * D_MODEL);
        mma_gemm<128, 128, 0, 0, true, true><<<dim3(4, 5, 16), 256>>>(
            o, Woutl, z, nullptr, NP1, D_MODEL, 512, HD, HD, D_MODEL,
            512, 512, 0, 0, 1.f);

        add_ln_kernel<<<NP1, 256>>>(x, z, ln1_s + l * D_MODEL, ln1_b + l * D_MODEL, x);

        mma_gemm<64, 64, 1, 0, false, true><<<dim3(8, 9, 1), 256>>>(
            x, F1l, h1, nullptr, NP1, D_MODEL, D_MODEL, D_MODEL, D_MODEL, D_MODEL,
            0, 0, 0, 0, 1.f);
        mma_gemm<64, 64, 0, 0, false, true><<<dim3(8, 9, 1), 256>>>(
            h1, F2l, z, nullptr, NP1, D_MODEL, D_MODEL, D_MODEL, D_MODEL, D_MODEL,
            0, 0, 0, 0, 1.f);

        float* lnout = (l == N_LAYER - 1) ? out : x;
        add_ln_kernel<<<NP1, 256>>>(x, z, ln2_s + l * D_MODEL, ln2_b + l * D_MODEL, lnout);
    }
}